// round 17
// baseline (speedup 1.0000x reference)
#include <cuda_runtime.h>
#include <cuda_fp16.h>

#define BATCH  128
#define TIME   256
#define FDIM   512
#define UNITS  1024
#define TP1    257
#define NRCTA  64          // recurrence CTAs
#define NGCTA  84          // GEMM CTAs
#define NCTA   (NRCTA + NGCTA)
#define NTHR   512

// ---- recurrence smem layout (bytes) ----
#define WT_STRIDE 2064                 // 1024 fp16 + 16B pad (conflict-free ldmatrix)
#define SM_WTH    0
#define SM_WTL    (16 * WT_STRIDE)     // 33024
#define SM_P      (2 * 16 * WT_STRIDE) // 66048 (4 partial buffers x 8192 B)
#define SM_TOTALB (SM_P + 4 * 8192)    // 98816  (GEMM path uses < 17KB of this)

// ---------------------------------------------------------------------------
// Global state in MMA fragment layout:
//   g_F[buf][ ((mt*64 + kt)*2 + part)*32 + lane ]  (uint4 = regs a0..a3)
// ---------------------------------------------------------------------------
__device__ __align__(256) uint4 g_F[2][8 * 64 * 2 * 32];   // 2 MB
__device__ unsigned g_qrdy[4];      // per-k-quarter publish counters (monotonic)
__device__ unsigned g_rdone;        // per-step read-done counter (monotonic)
__device__ unsigned g_hcnt[TIME];   // per-timestep h readiness (16 tiles each)

// ---------------------------------------------------------------------------
// PTX helpers (baseline ISA only — safe under compute_103 virtual arch)
// ---------------------------------------------------------------------------
__device__ __forceinline__ unsigned smem_u32(const void* p) {
    unsigned a;
    asm("{ .reg .u64 t; cvta.to.shared.u64 t, %1; cvt.u32.u64 %0, t; }"
        : "=r"(a) : "l"(p));
    return a;
}
__device__ __forceinline__ unsigned ldacq(const unsigned* p) {
    unsigned v;
    asm volatile("ld.acquire.gpu.global.u32 %0, [%1];" : "=r"(v) : "l"(p));
    return v;
}
__device__ __forceinline__ void ldm4(unsigned a, unsigned r[4]) {
    asm volatile("ldmatrix.sync.aligned.m8n8.x4.shared.b16 {%0,%1,%2,%3}, [%4];"
                 : "=r"(r[0]), "=r"(r[1]), "=r"(r[2]), "=r"(r[3]) : "r"(a));
}
__device__ __forceinline__ void mma_f16(float c[4], uint4 a,
                                        unsigned b0, unsigned b1) {
    asm volatile(
        "mma.sync.aligned.m16n8k16.row.col.f32.f16.f16.f32 "
        "{%0,%1,%2,%3}, {%4,%5,%6,%7}, {%8,%9}, {%0,%1,%2,%3};"
        : "+f"(c[0]), "+f"(c[1]), "+f"(c[2]), "+f"(c[3])
        : "r"(a.x), "r"(a.y), "r"(a.z), "r"(a.w), "r"(b0), "r"(b1));
}
__device__ __forceinline__ void ffma2(unsigned long long& d,
                                      unsigned long long a,
                                      unsigned long long b) {
    asm("fma.rn.f32x2 %0, %1, %2, %0;" : "+l"(d) : "l"(a), "l"(b));
}
__device__ __forceinline__ float2 u2f2(unsigned long long v) {
    float2 f;
    f.x = __uint_as_float((unsigned)(v & 0xffffffffu));
    f.y = __uint_as_float((unsigned)(v >> 32));
    return f;
}
// Fast tanh: 1 - 2/(e^{2x}+1).  __expf rel err ~2^-22; stable at both tails.
__device__ __forceinline__ float ftanh(float x) {
    float e = __expf(2.0f * x);
    return 1.0f - __fdividef(2.0f, e + 1.0f);
}

// ---------------------------------------------------------------------------
// Reset kernel: zero per-launch counters (graph-replay determinism).
// ---------------------------------------------------------------------------
__global__ void reset_kernel() {
    if (threadIdx.x < TIME) g_hcnt[threadIdx.x] = 0u;
    if (threadIdx.x < 4)    g_qrdy[threadIdx.x] = 0u;
    if (threadIdx.x == 4)   g_rdone = 0u;
}

// ---------------------------------------------------------------------------
// GEMM body (CTAs 64..147): h = X@R + bias -> out[b][t][:], t-major tiles.
// Tile: 64 m-rows (one t, half the batch) x 128 n-cols, BK=16, 512 threads,
// thread tile 4x4, FFMA2. After each tile: release-fence + g_hcnt[t]++.
// ---------------------------------------------------------------------------
#define ASTRIDE 132

__device__ void gemm_body(const float* __restrict__ X,
                          const float* __restrict__ R,
                          const float* __restrict__ bias,
                          float* __restrict__ out,
                          char* smem, int cid)
{
    float* Asd = (float*)smem;               // [16][132] duplicated A
    float* Bs  = (float*)smem + 16 * ASTRIDE; // [16][128]

    const int tid = threadIdx.x;
    const int tx  = tid & 31;       // n quad
    const int ty  = tid >> 5;       // m quad (0..15)
    const int li  = tid >> 2;       // A row (tid<256)
    const int lj  = (tid & 3) * 4;  // A k offset
    const int rj  = tid >> 5;       // B k row (0..15)
    const int ri  = (tid & 31) * 4; // B col

    for (int tau = cid; tau < 4096; tau += NGCTA) {
        const int t    = tau >> 4;
        const int sub  = tau & 15;
        const int bb0  = (sub & 1) * 64;
        const int col0 = (sub >> 1) * 128;

        unsigned long long cc[4][2];
        #pragma unroll
        for (int i = 0; i < 4; i++) { cc[i][0] = 0ULL; cc[i][1] = 0ULL; }

        const float* Xrow = X + ((size_t)(bb0 + li) * TIME + t) * FDIM;
        float4 a, b;
        if (tid < 256) a = *(const float4*)(Xrow + lj);
        b = *(const float4*)(R + (size_t)rj * UNITS + col0 + ri);

        for (int k0 = 0; k0 < FDIM; k0 += 16) {
            if (tid < 256) {
                *(float2*)(Asd + (lj + 0) * ASTRIDE + li * 2) = make_float2(a.x, a.x);
                *(float2*)(Asd + (lj + 1) * ASTRIDE + li * 2) = make_float2(a.y, a.y);
                *(float2*)(Asd + (lj + 2) * ASTRIDE + li * 2) = make_float2(a.z, a.z);
                *(float2*)(Asd + (lj + 3) * ASTRIDE + li * 2) = make_float2(a.w, a.w);
            }
            *(float4*)(Bs + rj * 128 + ri) = b;
            __syncthreads();

            if (k0 + 16 < FDIM) {
                if (tid < 256) a = *(const float4*)(Xrow + k0 + 16 + lj);
                b = *(const float4*)(R + (size_t)(k0 + 16 + rj) * UNITS + col0 + ri);
            }

            #pragma unroll
            for (int k = 0; k < 16; k++) {
                ulonglong2 a01 = *(const ulonglong2*)(Asd + k * ASTRIDE + ty * 8);
                ulonglong2 a23 = *(const ulonglong2*)(Asd + k * ASTRIDE + ty * 8 + 4);
                ulonglong2 bv  = *(const ulonglong2*)(Bs + k * 128 + tx * 4);
                ffma2(cc[0][0], a01.x, bv.x); ffma2(cc[0][1], a01.x, bv.y);
                ffma2(cc[1][0], a01.y, bv.x); ffma2(cc[1][1], a01.y, bv.y);
                ffma2(cc[2][0], a23.x, bv.x); ffma2(cc[2][1], a23.x, bv.y);
                ffma2(cc[3][0], a23.y, bv.x); ffma2(cc[3][1], a23.y, bv.y);
            }
            __syncthreads();
        }

        float4 bv4 = __ldg((const float4*)(bias + col0 + tx * 4));
        #pragma unroll
        for (int i = 0; i < 4; i++) {
            int bb = bb0 + ty * 4 + i;
            float2 lo = u2f2(cc[i][0]);
            float2 hi = u2f2(cc[i][1]);
            float4 v;
            v.x = lo.x + bv4.x; v.y = lo.y + bv4.y;
            v.z = hi.x + bv4.z; v.w = hi.y + bv4.w;
            *(float4*)(out + ((size_t)bb * TP1 + t) * UNITS + col0 + tx * 4) = v;
        }
        __syncthreads();
        if (tid == 0) {
            __threadfence();
            atomicAdd(&g_hcnt[t], 1u);
        }
    }
}

// ---------------------------------------------------------------------------
// Recurrence body (CTAs 0..63): persistent HMMA, fragment-resident state,
// flow-controlled (per-quarter producer counters; no global barrier).
// ---------------------------------------------------------------------------
__device__ void recur_body(const float* __restrict__ W,
                           const float* __restrict__ x0,
                           float* __restrict__ out,
                           char* smem)
{
    const unsigned sb = smem_u32(smem);
    const int tid = threadIdx.x;
    const int wid = tid >> 5;
    const int lid = tid & 31;
    const int u0  = blockIdx.x * 16;
    const int ktC = blockIdx.x;
    const int qC  = ktC >> 4;          // this CTA's publish quarter

    // W slice -> SMEM fp16 hi/lo, Wt[n][k], padded rows.
    for (int idx = tid; idx < 16 * UNITS; idx += NTHR) {
        int n = idx & 15;
        int k = idx >> 4;
        float v = __ldg(W + (size_t)k * UNITS + u0 + n);
        __half hi = __float2half_rn(v);
        __half lo = __float2half_rn(v - __half2float(hi));
        *(__half*)(smem + SM_WTH + n * WT_STRIDE + k * 2) = hi;
        *(__half*)(smem + SM_WTL + n * WT_STRIDE + k * 2) = lo;
    }

    // Epilogue / fragment-write mapping.
    const int er    = tid >> 2;
    const int ec    = (tid & 3) * 4;
    const int mtE   = er >> 4;
    const int rr    = er & 15;
    const int laneA = (rr & 7) * 4 + ((ec >> 1) & 3);
    const int regE  = (rr >> 3) + 2 * (ec >> 3);
    const unsigned fragBaseRel = (unsigned)(((mtE * 64 + ktC) * 2) * 32);

    // Init state buffer 0 with x0 (fragment layout), then publish quarter.
    {
        unsigned* fb = (unsigned*)(g_F[0] + fragBaseRel);
        #pragma unroll
        for (int j = 0; j < 2; j++) {
            float v0 = x0[u0 + ec + 2 * j];
            float v1 = x0[u0 + ec + 2 * j + 1];
            __half h0 = __float2half_rn(v0);
            __half h1 = __float2half_rn(v1);
            __half l0 = __float2half_rn(v0 - __half2float(h0));
            __half l1 = __float2half_rn(v1 - __half2float(h1));
            unsigned pH = (unsigned)__half_as_ushort(h0)
                        | ((unsigned)__half_as_ushort(h1) << 16);
            unsigned pL = (unsigned)__half_as_ushort(l0)
                        | ((unsigned)__half_as_ushort(l1) << 16);
            fb[(laneA + j) * 4 + regE]       = pH;
            fb[128 + (laneA + j) * 4 + regE] = pL;
        }
    }
    __syncthreads();
    if (tid == 0) {
        __threadfence();
        atomicAdd(&g_qrdy[qC], 1u);   // input of step 0 published
    }

    const int mg  = wid & 3;
    const int kh  = wid >> 2;          // k-quarter consumed by this warp
    const int rb  = mg * 32;
    const int mt0 = mg * 2;
    const int b_n    = (lid & 7) | ((lid >> 1) & 8);
    const int b_koff = ((lid >> 3) & 1) * 16;
    const unsigned bofl = (unsigned)(b_n * WT_STRIDE + b_koff);

    const size_t outbase = ((size_t)er * TP1) * UNITS + u0 + ec;

    float es[4] = {0.f, 0.f, 0.f, 0.f};
    int cur = 0;

    for (int t = 0; t < TIME; t++) {
        // ---- warp-level input wait: quarter kh published for step t
        {
            const unsigned need = 16u * (unsigned)(t + 1);
            while (ldacq(&g_qrdy[kh]) < need) { __nanosleep(30); }
            __syncwarp();
        }

        float acc[2][2][4];
        #pragma unroll
        for (int mi = 0; mi < 2; mi++)
            #pragma unroll
            for (int ni = 0; ni < 2; ni++)
                #pragma unroll
                for (int q = 0; q < 4; q++) acc[mi][ni][q] = 0.0f;

        const uint4* F = g_F[cur];
        uint4 f[8];
        {
            int kt = kh * 16;
            const uint4* p0 = F + mt0 * 4096 + kt * 64 + lid;
            const uint4* p1 = p0 + 4096;
            f[0] = __ldcg(p0);       f[1] = __ldcg(p0 + 32);
            f[2] = __ldcg(p1);       f[3] = __ldcg(p1 + 32);
            f[4] = __ldcg(p0 + 64);  f[5] = __ldcg(p0 + 96);
            f[6] = __ldcg(p1 + 64);  f[7] = __ldcg(p1 + 96);
        }

        for (int sc = 0; sc < 8; sc++) {
            uint4 nf[8];
            if (sc < 7) {
                int kt = kh * 16 + sc * 2 + 2;
                const uint4* p0 = F + mt0 * 4096 + kt * 64 + lid;
                const uint4* p1 = p0 + 4096;
                nf[0] = __ldcg(p0);       nf[1] = __ldcg(p0 + 32);
                nf[2] = __ldcg(p1);       nf[3] = __ldcg(p1 + 32);
                nf[4] = __ldcg(p0 + 64);  nf[5] = __ldcg(p0 + 96);
                nf[6] = __ldcg(p1 + 64);  nf[7] = __ldcg(p1 + 96);
            }

            #pragma unroll
            for (int q = 0; q < 2; q++) {
                int kt = kh * 16 + sc * 2 + q;
                unsigned bh[4], bl[4];
                ldm4(sb + SM_WTH + bofl + (unsigned)(kt * 32), bh);
                ldm4(sb + SM_WTL + bofl + (unsigned)(kt * 32), bl);

                uint4 ah0 = f[q * 4 + 0], al0 = f[q * 4 + 1];
                uint4 ah1 = f[q * 4 + 2], al1 = f[q * 4 + 3];

                mma_f16(acc[0][0], ah0, bh[0], bh[1]);
                mma_f16(acc[0][1], ah0, bh[2], bh[3]);
                mma_f16(acc[1][0], ah1, bh[0], bh[1]);
                mma_f16(acc[1][1], ah1, bh[2], bh[3]);
                mma_f16(acc[0][0], ah0, bl[0], bl[1]);
                mma_f16(acc[0][1], ah0, bl[2], bl[3]);
                mma_f16(acc[1][0], ah1, bl[0], bl[1]);
                mma_f16(acc[1][1], ah1, bl[2], bl[3]);
                mma_f16(acc[0][0], al0, bh[0], bh[1]);
                mma_f16(acc[0][1], al0, bh[2], bh[3]);
                mma_f16(acc[1][0], al1, bh[0], bh[1]);
                mma_f16(acc[1][1], al1, bh[2], bh[3]);
            }

            if (sc < 7) {
                #pragma unroll
                for (int i = 0; i < 8; i++) f[i] = nf[i];
            }
        }

        // ---- store k-quarter partials
        {
            float* P = (float*)(smem + SM_P + kh * 8192);
            int pr = rb + (lid >> 2);
            int pc = (lid & 3) * 2;
            #pragma unroll
            for (int mi = 0; mi < 2; mi++)
                #pragma unroll
                for (int ni = 0; ni < 2; ni++) {
                    int base = (pr + mi * 16) * 16 + ni * 8 + pc;
                    *(float2*)(P + base) =
                        make_float2(acc[mi][ni][0], acc[mi][ni][1]);
                    *(float2*)(P + base + 128) =
                        make_float2(acc[mi][ni][2], acc[mi][ni][3]);
                }
        }
        __syncthreads();   // all warps' frag reads + partial stores complete

        // ---- signal read-done; wait h[t]; wait WAR clearance for frag writes
        if (tid == 0) {
            atomicAdd(&g_rdone, 1u);                   // our buf[t&1] reads done
            while (*(volatile unsigned*)&g_hcnt[t] < 16u) { __nanosleep(30); }
            if (t >= 1 && t + 1 < TIME) {
                const unsigned need = 64u * (unsigned)t;
                while (*(volatile unsigned*)&g_rdone < need) { __nanosleep(30); }
            }
            __threadfence();
        }
        __syncthreads();

        // ---- epilogue: reduce 4 quarters, tanh, exp, write out + state frags
        {
            float4 h = __ldg((const float4*)(out + outbase + (size_t)t * UNITS));

            const float* P0 = (const float*)(smem + SM_P) + er * 16 + ec;
            float4 p0 = *(const float4*)P0;
            float4 p1 = *(const float4*)(P0 + 2048);
            float4 p2 = *(const float4*)(P0 + 4096);
            float4 p3 = *(const float4*)(P0 + 6144);

            float s[4];
            s[0] = ftanh(h.x + ((p0.x + p1.x) + (p2.x + p3.x)));
            s[1] = ftanh(h.y + ((p0.y + p1.y) + (p2.y + p3.y)));
            s[2] = ftanh(h.z + ((p0.z + p1.z) + (p2.z + p3.z)));
            s[3] = ftanh(h.w + ((p0.w + p1.w) + (p2.w + p3.w)));

            if (t + 1 < TIME) {
                unsigned* fb = (unsigned*)(g_F[cur ^ 1] + fragBaseRel);
                #pragma unroll
                for (int j = 0; j < 2; j++) {
                    float v0 = s[2 * j], v1 = s[2 * j + 1];
                    __half h0v = __float2half_rn(v0);
                    __half h1v = __float2half_rn(v1);
                    __half l0v = __float2half_rn(v0 - __half2float(h0v));
                    __half l1v = __float2half_rn(v1 - __half2float(h1v));
                    unsigned pH = (unsigned)__half_as_ushort(h0v)
                                | ((unsigned)__half_as_ushort(h1v) << 16);
                    unsigned pL = (unsigned)__half_as_ushort(l0v)
                                | ((unsigned)__half_as_ushort(l1v) << 16);
                    fb[(laneA + j) * 4 + regE]       = pH;
                    fb[128 + (laneA + j) * 4 + regE] = pL;
                }
            }

            *(float4*)(out + outbase + (size_t)t * UNITS)
                = make_float4(s[0], s[1], s[2], s[3]);

            es[0] += __expf(s[0]);
            es[1] += __expf(s[1]);
            es[2] += __expf(s[2]);
            es[3] += __expf(s[3]);
        }

        cur ^= 1;
        if (t + 1 < TIME) {
            __syncthreads();   // frag stores + P reads complete
            if (tid == 0) {
                __threadfence();
                atomicAdd(&g_qrdy[qC], 1u);   // input of step t+1 published
            }
        }
    }

    // terminal row
    {
        const float inv = 1.0f / (float)TIME;
        float4 tm;
        tm.x = logf(tanhf(es[0] * inv));
        tm.y = logf(tanhf(es[1] * inv));
        tm.z = logf(tanhf(es[2] * inv));
        tm.w = logf(tanhf(es[3] * inv));
        *(float4*)(out + outbase + (size_t)TIME * UNITS) = tm;
    }
}

// ---------------------------------------------------------------------------
// Fused kernel: CTAs 0..63 recurrence, 64..147 h-projection GEMM.
// ---------------------------------------------------------------------------
__global__ void __launch_bounds__(NTHR) fused_kernel(
    const float* __restrict__ X,
    const float* __restrict__ R,
    const float* __restrict__ W,
    const float* __restrict__ bias,
    const float* __restrict__ x0,
    float* __restrict__ out)
{
    extern __shared__ __align__(128) char smem[];
    if (blockIdx.x < NRCTA) {
        recur_body(W, x0, out, smem);
    } else {
        gemm_body(X, R, bias, out, smem, blockIdx.x - NRCTA);
    }
}

// ---------------------------------------------------------------------------
// Launch
// ---------------------------------------------------------------------------
extern "C" void kernel_launch(void* const* d_in, const int* in_sizes, int n_in,
                              void* d_out, int out_size) {
    const float* X    = (const float*)d_in[0];  // [128,256,512]
    const float* R    = (const float*)d_in[1];  // [512,1024]
    const float* W    = (const float*)d_in[2];  // [1024,1024]
    const float* bias = (const float*)d_in[3];  // [1024]
    const float* x0   = (const float*)d_in[4];  // [1024]
    float* out = (float*)d_out;                 // [128,257,1024]

    (void)in_sizes; (void)n_in; (void)out_size;

    reset_kernel<<<1, 256>>>();

    cudaFuncSetAttribute(fused_kernel,
                         cudaFuncAttributeMaxDynamicSharedMemorySize, SM_TOTALB);
    fused_kernel<<<NCTA, NTHR, SM_TOTALB>>>(X, R, W, bias, x0, out);
}